// round 2
// baseline (speedup 1.0000x reference)
#include <cuda_runtime.h>
#include <cuda_bf16.h>
#include <math.h>

// Problem constants (fixed by the dataset)
#define IN_DIM   512
#define OUT_DIM  512
#define BATCH    16384
#define N_COEFFS 8          // spline coeffs per input dim
#define N_KNOTS  12
#define KPD      9          // virtual K per input dim: 8 spline + 1 silu/base

#define BM 128
#define BN 128
#define BKD 4               // input dims per K-tile
#define KK  (BKD * KPD)     // 36 virtual k per tile
#define NTHREADS 256

// Precomputed grid scratch (tiny; __device__ globals are the allowed scratch)
__device__ float g_knots[IN_DIM * N_KNOTS];     // 24.6 KB
__device__ float g_rden [IN_DIM * (N_KNOTS-1)]; // 22.5 KB (1/(denom+eps))

// ---------------------------------------------------------------------------
// Kernel 1: per-dim knot vector + reciprocal denominators
// grid[j] = start + cumsum(softplus(steps_log))
// ---------------------------------------------------------------------------
__global__ void grid_precompute_kernel(const float* __restrict__ steps_log,
                                       const float* __restrict__ grid_start)
{
    int i = blockIdx.x * blockDim.x + threadIdx.x;
    if (i >= IN_DIM) return;
    float kn[N_KNOTS];
    kn[0] = grid_start[i];
    float acc = kn[0];
    #pragma unroll
    for (int j = 0; j < N_KNOTS - 1; j++) {
        float v  = steps_log[i * (N_KNOTS-1) + j];
        float sp = fmaxf(v, 0.0f) + log1pf(expf(-fabsf(v)));  // stable softplus
        acc += sp;
        kn[j+1] = acc;
    }
    #pragma unroll
    for (int j = 0; j < N_KNOTS; j++) g_knots[i * N_KNOTS + j] = kn[j];
    #pragma unroll
    for (int j = 0; j < N_KNOTS - 1; j++)
        g_rden[i * (N_KNOTS-1) + j] = 1.0f / (kn[j+1] - kn[j] + 1e-8f);
}

// ---------------------------------------------------------------------------
// Degree-3 basis exactly replicating the reference recursion
// (note: denominators are ADJACENT knot spacings at every level — a quirk of
//  the reference implementation, reproduced verbatim)
// ---------------------------------------------------------------------------
__device__ __forceinline__ void eval_basis(float xv,
                                           const float* __restrict__ k,
                                           const float* __restrict__ rd,
                                           float* __restrict__ out8)
{
    float t[11];
    #pragma unroll
    for (int j = 0; j < 11; j++)
        t[j] = (xv >= k[j] && xv < k[j+1]) ? 1.0f : 0.0f;
    #pragma unroll
    for (int j = 0; j < 10; j++)   // k=0
        t[j] = (xv - k[j]) * rd[j] * t[j] + (k[j+2] - xv) * rd[j+1] * t[j+1];
    #pragma unroll
    for (int j = 0; j < 9; j++)    // k=1
        t[j] = (xv - k[j]) * rd[j] * t[j] + (k[j+3] - xv) * rd[j+2] * t[j+1];
    #pragma unroll
    for (int j = 0; j < 8; j++)    // k=2
        out8[j] = (xv - k[j]) * rd[j] * t[j] + (k[j+4] - xv) * rd[j+3] * t[j+1];
}

// ---------------------------------------------------------------------------
// Kernel 2: fused KAN layer.  out[b,o] = tanh( sum_k A[b,k]*W[o,k] + rs*x[b,o] )
// A generated on the fly: per dim i -> 8 spline bases + silu(x).
// ---------------------------------------------------------------------------
__global__ __launch_bounds__(NTHREADS, 2)
void kan_fused_kernel(const float* __restrict__ x,
                      const float* __restrict__ coeffs,      // [OUT, IN*8]
                      const float* __restrict__ base_weight, // [OUT, IN]
                      const float* __restrict__ res_scale,   // [1]
                      float* __restrict__ out)
{
    __shared__ float As[KK * BM];      // [kk][row]  18 KB
    __shared__ float Bs[KK * BN];      // [kk][col]  18 KB
    __shared__ float xs[BM * 5];       // [row][d], stride 5 (bank-friendly)
    __shared__ float ks[BKD * N_KNOTS];
    __shared__ float rds[BKD * (N_KNOTS-1)];

    const int t  = threadIdx.x;
    const int tx = t & 15;             // 0..15 (cols)
    const int ty = t >> 4;             // 0..15 (rows)
    const int col0 = blockIdx.x * BN;
    const int row0 = blockIdx.y * BM;

    float acc[8][8];
    #pragma unroll
    for (int i = 0; i < 8; i++)
        #pragma unroll
        for (int j = 0; j < 8; j++) acc[i][j] = 0.0f;

    const int o_l  = t >> 1;           // 0..127, for B-tile load
    const int half = t & 1;
    const int o_g  = col0 + o_l;

    for (int i0 = 0; i0 < IN_DIM; i0 += BKD) {
        __syncthreads();   // previous main loop finished reading smem

        // ---- stage x rows (float4 contiguous over 4 dims) ----
        if (t < BM) {
            float4 xv4 = *reinterpret_cast<const float4*>(
                &x[(size_t)(row0 + t) * IN_DIM + i0]);
            xs[t*5 + 0] = xv4.x; xs[t*5 + 1] = xv4.y;
            xs[t*5 + 2] = xv4.z; xs[t*5 + 3] = xv4.w;
        }
        // ---- stage knots / reciprocal denoms for these 4 dims ----
        if (t >= 128 && t < 128 + BKD * N_KNOTS)
            ks[t - 128] = g_knots[i0 * N_KNOTS + (t - 128)];
        if (t >= 176 && t < 176 + BKD * (N_KNOTS-1))
            rds[t - 176] = g_rden[i0 * (N_KNOTS-1) + (t - 176)];

        // ---- stage weight tile: 36 x 128 ----
        {
            #pragma unroll
            for (int dd = 0; dd < 2; dd++) {
                int d = half * 2 + dd;
                const float4* p = reinterpret_cast<const float4*>(
                    &coeffs[(size_t)o_g * (IN_DIM * N_COEFFS) + (i0 + d) * N_COEFFS]);
                float4 v0 = p[0], v1 = p[1];
                int kb = (d * KPD) * BN + o_l;
                Bs[kb + 0*BN] = v0.x; Bs[kb + 1*BN] = v0.y;
                Bs[kb + 2*BN] = v0.z; Bs[kb + 3*BN] = v0.w;
                Bs[kb + 4*BN] = v1.x; Bs[kb + 5*BN] = v1.y;
                Bs[kb + 6*BN] = v1.z; Bs[kb + 7*BN] = v1.w;
            }
            if (half == 0) {
                float4 w = *reinterpret_cast<const float4*>(
                    &base_weight[(size_t)o_g * IN_DIM + i0]);
                Bs[(0*KPD + 8)*BN + o_l] = w.x;
                Bs[(1*KPD + 8)*BN + o_l] = w.y;
                Bs[(2*KPD + 8)*BN + o_l] = w.z;
                Bs[(3*KPD + 8)*BN + o_l] = w.w;
            }
        }
        __syncthreads();   // xs/ks/rds ready

        // ---- compute A tile: 512 elements, 2 per thread ----
        #pragma unroll
        for (int m = 0; m < 2; m++) {
            int e   = t + m * NTHREADS;
            int d   = e >> 7;
            int row = e & 127;
            float xv = xs[row*5 + d];
            float bb[8];
            eval_basis(xv, &ks[d * N_KNOTS], &rds[d * (N_KNOTS-1)], bb);
            int kb = (d * KPD) * BM + row;
            #pragma unroll
            for (int c = 0; c < 8; c++) As[kb + c*BM] = bb[c];
            As[kb + 8*BM] = xv / (1.0f + expf(-xv));   // silu
        }
        __syncthreads();   // As/Bs ready

        // ---- main FMA loop: 36 virtual k ----
        #pragma unroll 6
        for (int kk = 0; kk < KK; kk++) {
            float4 a0 = *reinterpret_cast<const float4*>(&As[kk*BM + ty*8]);
            float4 a1 = *reinterpret_cast<const float4*>(&As[kk*BM + ty*8 + 4]);
            float4 b0 = *reinterpret_cast<const float4*>(&Bs[kk*BN + tx*8]);
            float4 b1 = *reinterpret_cast<const float4*>(&Bs[kk*BN + tx*8 + 4]);
            float a[8] = {a0.x,a0.y,a0.z,a0.w,a1.x,a1.y,a1.z,a1.w};
            float b[8] = {b0.x,b0.y,b0.z,b0.w,b1.x,b1.y,b1.z,b1.w};
            #pragma unroll
            for (int i = 0; i < 8; i++)
                #pragma unroll
                for (int j = 0; j < 8; j++)
                    acc[i][j] = fmaf(a[i], b[j], acc[i][j]);
        }
    }

    // ---- epilogue: + rs*x, tanh, coalesced float4 stores ----
    const float rs = __ldg(res_scale);
    #pragma unroll
    for (int i = 0; i < 8; i++) {
        int row = row0 + ty*8 + i;
        size_t base = (size_t)row * OUT_DIM + col0 + tx*8;
        float4 xv0 = *reinterpret_cast<const float4*>(&x[base]);
        float4 xv1 = *reinterpret_cast<const float4*>(&x[base + 4]);
        float4 o0, o1;
        o0.x = tanhf(acc[i][0] + rs * xv0.x);
        o0.y = tanhf(acc[i][1] + rs * xv0.y);
        o0.z = tanhf(acc[i][2] + rs * xv0.z);
        o0.w = tanhf(acc[i][3] + rs * xv0.w);
        o1.x = tanhf(acc[i][4] + rs * xv1.x);
        o1.y = tanhf(acc[i][5] + rs * xv1.y);
        o1.z = tanhf(acc[i][6] + rs * xv1.z);
        o1.w = tanhf(acc[i][7] + rs * xv1.w);
        *reinterpret_cast<float4*>(&out[base])     = o0;
        *reinterpret_cast<float4*>(&out[base + 4]) = o1;
    }
}

// ---------------------------------------------------------------------------
extern "C" void kernel_launch(void* const* d_in, const int* in_sizes, int n_in,
                              void* d_out, int out_size)
{
    const float* x           = (const float*)d_in[0];
    const float* coeffs      = (const float*)d_in[1];
    const float* base_weight = (const float*)d_in[2];
    const float* steps_log   = (const float*)d_in[3];
    const float* grid_start  = (const float*)d_in[4];
    const float* res_scale   = (const float*)d_in[5];
    float* out = (float*)d_out;

    grid_precompute_kernel<<<(IN_DIM + 255) / 256, 256>>>(steps_log, grid_start);

    dim3 grid(OUT_DIM / BN, BATCH / BM);   // (4, 128)
    kan_fused_kernel<<<grid, NTHREADS>>>(x, coeffs, base_weight, res_scale, out);
}

// round 6
// speedup vs baseline: 2.2743x; 2.2743x over previous
#include <cuda_runtime.h>
#include <cuda_bf16.h>
#include <cstdint>
#include <math.h>

// ---------------- problem constants ----------------
#define IN_DIM   512
#define OUT_DIM  512
#define BATCH    16384
#define N_COEFFS 8
#define N_KNOTS  12
#define K_SPLINE (IN_DIM * N_COEFFS)     // 4096
#define K_TOTAL  (K_SPLINE + IN_DIM)     // 4608

// ---------------- GEMM tiling ----------------
#define BM 128
#define BN 128
#define BK 32
#define NTILES (K_TOTAL / BK)            // 144
#define SPLIT_TILE (K_SPLINE / BK)       // 128: source switch
#define NTHREADS 256

// smem: [stage][A 128x36f | B 128x36f]
#define TILE_F  (128 * 36)               // floats per tile (padded stride 36)
#define STAGE_F (2 * TILE_F)
#define SMEM_BYTES (2 * STAGE_F * 4)     // 73,728

// ---------------- device scratch (static, no allocs) ----------------
__device__ float g_knots[IN_DIM * N_KNOTS];
__device__ float g_rden [IN_DIM * (N_KNOTS - 1)];
__device__ float g_A [(size_t)BATCH * K_SPLINE];   // tf32-rounded spline basis
__device__ float g_S [(size_t)BATCH * IN_DIM];     // tf32-rounded silu(x)
__device__ float g_Wc[(size_t)OUT_DIM * K_SPLINE]; // tf32-rounded coeffs
__device__ float g_Wb[(size_t)OUT_DIM * IN_DIM];   // tf32-rounded base_weight

// ---------------- helpers ----------------
__device__ __forceinline__ float f2tf32(float f) {
    uint32_t o;
    asm("cvt.rna.tf32.f32 %0, %1;" : "=r"(o) : "f"(f));
    return __uint_as_float(o);
}
#define CP16(dst, src) asm volatile("cp.async.cg.shared.global [%0], [%1], 16;" :: "r"(dst), "l"(src) : "memory")
#define CP_COMMIT()    asm volatile("cp.async.commit_group;" ::: "memory")
#define CP_WAIT1()     asm volatile("cp.async.wait_group 1;" ::: "memory")
#define CP_WAIT0()     asm volatile("cp.async.wait_group 0;" ::: "memory")

__device__ __forceinline__ uint32_t smem_u32(const void* p) {
    uint32_t a;
    asm("{ .reg .u64 t; cvta.to.shared.u64 t, %1; cvt.u32.u64 %0, t; }" : "=r"(a) : "l"(p));
    return a;
}

__device__ __forceinline__ void mma_tf32(float* c, const uint32_t* a, uint32_t b0, uint32_t b1) {
    asm volatile(
        "mma.sync.aligned.m16n8k8.row.col.f32.tf32.tf32.f32 "
        "{%0,%1,%2,%3}, {%4,%5,%6,%7}, {%8,%9}, {%0,%1,%2,%3};"
        : "+f"(c[0]), "+f"(c[1]), "+f"(c[2]), "+f"(c[3])
        : "r"(a[0]), "r"(a[1]), "r"(a[2]), "r"(a[3]), "r"(b0), "r"(b1));
}

// ---------------- kernel 1: knot precompute ----------------
__global__ void grid_precompute_kernel(const float* __restrict__ steps_log,
                                       const float* __restrict__ grid_start)
{
    int i = blockIdx.x * blockDim.x + threadIdx.x;
    if (i >= IN_DIM) return;
    float kn[N_KNOTS];
    kn[0] = grid_start[i];
    float acc = kn[0];
    #pragma unroll
    for (int j = 0; j < N_KNOTS - 1; j++) {
        float v  = steps_log[i * (N_KNOTS - 1) + j];
        float sp = fmaxf(v, 0.0f) + log1pf(expf(-fabsf(v)));
        acc += sp;
        kn[j + 1] = acc;
    }
    #pragma unroll
    for (int j = 0; j < N_KNOTS; j++) g_knots[i * N_KNOTS + j] = kn[j];
    #pragma unroll
    for (int j = 0; j < N_KNOTS - 1; j++)
        g_rden[i * (N_KNOTS - 1) + j] = 1.0f / (kn[j + 1] - kn[j] + 1e-8f);
}

// ---------------- kernel 2: weight pre-rounding to tf32 ----------------
__global__ void convert_weights_kernel(const float* __restrict__ coeffs,
                                       const float* __restrict__ base_weight)
{
    int n = OUT_DIM * K_SPLINE;        // 2,097,152
    int nb = OUT_DIM * IN_DIM;         // 262,144
    for (int i = blockIdx.x * blockDim.x + threadIdx.x; i < n; i += gridDim.x * blockDim.x)
        g_Wc[i] = f2tf32(coeffs[i]);
    for (int i = blockIdx.x * blockDim.x + threadIdx.x; i < nb; i += gridDim.x * blockDim.x)
        g_Wb[i] = f2tf32(base_weight[i]);
}

// ---------------- kernel 3: basis + silu generation ----------------
// block: 512 threads (one per input dim), 8 batch rows per block
#define ROWS_PER_BLK 8
__global__ __launch_bounds__(512)
void basis_kernel(const float* __restrict__ x)
{
    const int d  = threadIdx.x;
    const int b0 = blockIdx.x * ROWS_PER_BLK;

    float k[N_KNOTS], rd[N_KNOTS - 1];
    #pragma unroll
    for (int j = 0; j < N_KNOTS; j++) k[j] = g_knots[d * N_KNOTS + j];
    #pragma unroll
    for (int j = 0; j < N_KNOTS - 1; j++) rd[j] = g_rden[d * (N_KNOTS - 1) + j];

    #pragma unroll
    for (int bi = 0; bi < ROWS_PER_BLK; bi++) {
        const int b = b0 + bi;
        const float xv = __ldg(x + (size_t)b * IN_DIM + d);

        float t[11];
        #pragma unroll
        for (int j = 0; j < 11; j++)
            t[j] = (xv >= k[j] && xv < k[j + 1]) ? 1.0f : 0.0f;
        #pragma unroll
        for (int j = 0; j < 10; j++)
            t[j] = (xv - k[j]) * rd[j] * t[j] + (k[j + 2] - xv) * rd[j + 1] * t[j + 1];
        #pragma unroll
        for (int j = 0; j < 9; j++)
            t[j] = (xv - k[j]) * rd[j] * t[j] + (k[j + 3] - xv) * rd[j + 2] * t[j + 1];
        float bb[8];
        #pragma unroll
        for (int j = 0; j < 8; j++)
            bb[j] = f2tf32((xv - k[j]) * rd[j] * t[j] + (k[j + 4] - xv) * rd[j + 3] * t[j + 1]);

        float* dst = g_A + (size_t)b * K_SPLINE + d * 8;
        *(float4*)(dst)     = make_float4(bb[0], bb[1], bb[2], bb[3]);
        *(float4*)(dst + 4) = make_float4(bb[4], bb[5], bb[6], bb[7]);
        g_S[(size_t)b * IN_DIM + d] = f2tf32(xv / (1.0f + expf(-xv)));
    }
}

// ---------------- kernel 4: tf32 mma.sync GEMM + epilogue ----------------
__global__ __launch_bounds__(NTHREADS, 2)
void kan_gemm_kernel(const float* __restrict__ x,
                     const float* __restrict__ res_scale,
                     float* __restrict__ out)
{
    extern __shared__ float smem[];

    const int t    = threadIdx.x;
    const int warp = t >> 5, lane = t & 31;
    const int q = lane >> 2, r = lane & 3;
    const int warpM = warp >> 1, warpN = warp & 1;     // 4 x 2
    const int m_blk = blockIdx.x * BM;
    const int n_blk = blockIdx.y * BN;

    const uint32_t sb = smem_u32(smem);
    const int row  = t >> 1;            // 0..127
    const int cb   = (t & 1) * 4;       // chunk base 0/4

    // ---- async tile loader (A rows = batch, B rows = out-features) ----
    auto load_tile = [&](int kt, int stage) {
        const float *Asrc, *Bsrc;
        size_t sA, sB;
        int kc;
        if (kt < SPLIT_TILE) { Asrc = g_A; sA = K_SPLINE; Bsrc = g_Wc; sB = K_SPLINE; kc = kt * BK; }
        else                 { Asrc = g_S; sA = IN_DIM;   Bsrc = g_Wb; sB = IN_DIM;   kc = (kt - SPLIT_TILE) * BK; }
        const uint32_t abase = sb + (uint32_t)(stage * STAGE_F) * 4;
        const uint32_t bbase = abase + TILE_F * 4;
        const float* ag = Asrc + (size_t)(m_blk + row) * sA + kc;
        const float* bg = Bsrc + (size_t)(n_blk + row) * sB + kc;
        #pragma unroll
        for (int j = 0; j < 4; j++) {
            const int c = cb + j;
            CP16(abase + row * 144 + c * 16, ag + c * 4);
            CP16(bbase + row * 144 + c * 16, bg + c * 4);
        }
        CP_COMMIT();
    };

    float acc[2][8][4];
    #pragma unroll
    for (int i = 0; i < 2; i++)
        #pragma unroll
        for (int j = 0; j < 8; j++)
            #pragma unroll
            for (int v = 0; v < 4; v++) acc[i][j][v] = 0.0f;

    load_tile(0, 0);

    for (int kt = 0; kt < NTILES; kt++) {
        if (kt + 1 < NTILES) { load_tile(kt + 1, (kt + 1) & 1); CP_WAIT1(); }
        else                 { CP_WAIT0(); }
        __syncthreads();

        const uint32_t* As = (const uint32_t*)(smem + (kt & 1) * STAGE_F);
        const uint32_t* Bs = As + TILE_F;

        #pragma unroll
        for (int ks = 0; ks < 4; ks++) {
            const int bk = ks * 8;
            uint32_t a[2][4];
            #pragma unroll
            for (int mf = 0; mf < 2; mf++) {
                const int m0 = (warpM * 32 + mf * 16 + q) * 36 + bk + r;
                a[mf][0] = As[m0];
                a[mf][1] = As[m0 + 8 * 36];
                a[mf][2] = As[m0 + 4];
                a[mf][3] = As[m0 + 8 * 36 + 4];
            }
            #pragma unroll
            for (int nf = 0; nf < 8; nf++) {
                const int nn = (warpN * 64 + nf * 8 + q) * 36 + bk + r;
                const uint32_t b0 = Bs[nn], b1 = Bs[nn + 4];
                mma_tf32(acc[0][nf], a[0], b0, b1);
                mma_tf32(acc[1][nf], a[1], b0, b1);
            }
        }
        __syncthreads();
    }

    // ---- epilogue: + rs*x, tanh ----
    const float rs = __ldg(res_scale);
    #pragma unroll
    for (int mf = 0; mf < 2; mf++) {
        #pragma unroll
        for (int rr = 0; rr < 2; rr++) {
            const int rowg = m_blk + warpM * 32 + mf * 16 + rr * 8 + q;
            #pragma unroll
            for (int nf = 0; nf < 8; nf++) {
                const int col = n_blk + warpN * 64 + nf * 8 + r * 2;
                const size_t idx = (size_t)rowg * OUT_DIM + col;
                const float2 xv = __ldg((const float2*)(x + idx));
                float2 o;
                o.x = tanhf(acc[mf][nf][rr * 2 + 0] + rs * xv.x);
                o.y = tanhf(acc[mf][nf][rr * 2 + 1] + rs * xv.y);
                *(float2*)(out + idx) = o;
            }
        }
    }
}

// ---------------------------------------------------------------------------
extern "C" void kernel_launch(void* const* d_in, const int* in_sizes, int n_in,
                              void* d_out, int out_size)
{
    const float* x           = (const float*)d_in[0];
    const float* coeffs      = (const float*)d_in[1];
    const float* base_weight = (const float*)d_in[2];
    const float* steps_log   = (const float*)d_in[3];
    const float* grid_start  = (const float*)d_in[4];
    const float* res_scale   = (const float*)d_in[5];
    float* out = (float*)d_out;

    grid_precompute_kernel<<<2, 256>>>(steps_log, grid_start);
    convert_weights_kernel<<<296, 256>>>(coeffs, base_weight);
    basis_kernel<<<BATCH / ROWS_PER_BLK, 512>>>(x);

    cudaFuncSetAttribute(kan_gemm_kernel,
                         cudaFuncAttributeMaxDynamicSharedMemorySize, SMEM_BYTES);
    dim3 grid(BATCH / BM, OUT_DIM / BN);   // (128, 4)
    kan_gemm_kernel<<<grid, NTHREADS, SMEM_BYTES>>>(x, res_scale, out);
}